// round 16
// baseline (speedup 1.0000x reference)
#include <cuda_runtime.h>

// Grouped 3-tap width conv with cyclic rolls, fp32. Single kernel node.
// Grid = 16 k-tiles x 7 heights = 112 blocks, 512 threads (16 warps).
// Fully warp-autonomous until the epilogue: each warp stages ITS OWN 32-row
// input slice (the mainloop only reads rows iB..iB+31) -> no block barrier
// before compute. Weights gmem->registers, triple-buffered. o-paired f32x2
// taps, conflict-free epilogue reduce.
//
// y[o,k,n,m] = sum_{i,j} f[o,i,m+j] * w[i,k,j],  f[1..7] = width-rolled x row,
// f[0]=f[8]=0 (taps dropped); height roll baked into the final store index.

#define THREADS  512

#define OFF_IN   0
#define SZ_IN    (512 * 64)        // input row i = 7 float2 (x0,x1) slots + pad
#define SMEM_TOT SZ_IN             // 32768 B; epilogue reduce overlays this
#define OFF_RED  0

typedef unsigned long long ull;

__device__ __forceinline__ ull ffma2(ull a, ull b, ull c)
{
    ull d;
    asm("fma.rn.f32x2 %0, %1, %2, %3;" : "=l"(d) : "l"(a), "l"(b), "l"(c));
    return d;
}
__device__ __forceinline__ ull dup2(float v)
{
    ull d;
    asm("mov.b64 %0, {%1, %1};" : "=l"(d) : "f"(v));
    return d;
}

__global__ __launch_bounds__(THREADS, 1) void conv_wp(const float* __restrict__ x,
                                                      const float* __restrict__ w,
                                                      float* __restrict__ out)
{
    extern __shared__ char sm[];
    const int tid = threadIdx.x, warp = tid >> 5, lane = tid & 31;
    const int kb  = blockIdx.x, n = blockIdx.y, k0 = kb * 32;
    const int iB  = warp * 32;           // warp-private i slice

    // ---- weight register pipeline: 4 chunks of 8 i, 3 buffers ----
    const float* wl = w + (long)iB * 1536 + (k0 + lane) * 3;

    float a0[8], a1[8], a2[8];
    float b0[8], b1[8], b2[8];
    float c0[8], c1[8], c2[8];

#define LOADW(d0, d1, d2, c) do { \
        const float* p_ = wl + (c) * (8 * 1536); \
        _Pragma("unroll") \
        for (int t = 0; t < 8; t++) { \
            d0[t] = p_[t * 1536]; \
            d1[t] = p_[t * 1536 + 1]; \
            d2[t] = p_[t * 1536 + 2]; \
        } \
    } while (0)

    LOADW(a0, a1, a2, 0);                // in flight under the staging shadow
    LOADW(b0, b1, b2, 1);
    LOADW(c0, c1, c2, 2);

    // ---- warp-private input staging: 64 rows (i-slice x 2 groups), 14/lane ----
    {
        int rl = lane / 7;               // local row 0..63 = o*32 + il
        int j  = lane - rl * 7;          // source width position
        const int nbase = n * 7;
#pragma unroll
        for (int q = 0; q < 14; q++) {
            int o  = rl >> 5, il = rl & 31;
            float v = x[(o * 512 + iB + il) * 49 + nbase + j];
            int u = (j == 6) ? 1 : (j + 2);            // width roll +1
            *reinterpret_cast<float*>(sm + OFF_IN + (iB + il) * 64 + (u - 1) * 8 + o * 4) = v;
            j += 4;
            if (j >= 7) { j -= 7; rl += 5; } else rl += 4;
        }
    }
    __syncwarp();                        // own slice visible; no block barrier

    ull A[7];
#pragma unroll
    for (int m = 0; m < 7; m++) A[m] = 0ull;

#define COMPUTE(c, s0, s1, s2) do { \
        const char* ip_ = sm + OFF_IN + ((iB + (c) * 8) << 6); \
        _Pragma("unroll") \
        for (int t = 0; t < 8; t++) { \
            const char* ib = ip_ + t * 64; \
            ulonglong2 L0 = *reinterpret_cast<const ulonglong2*>(ib);       /* f1,f2 */ \
            ulonglong2 L1 = *reinterpret_cast<const ulonglong2*>(ib + 16);  /* f3,f4 */ \
            ulonglong2 L2 = *reinterpret_cast<const ulonglong2*>(ib + 32);  /* f5,f6 */ \
            ull        p7 = *reinterpret_cast<const ull*>(ib + 48);         /* f7 */ \
            ull W0 = dup2(s0[t]), W1 = dup2(s1[t]), W2 = dup2(s2[t]); \
            ull p1 = L0.x, p2 = L0.y, p3 = L1.x, p4 = L1.y, p5 = L2.x, p6 = L2.y; \
            A[0] = ffma2(p1, W1, A[0]); A[0] = ffma2(p2, W2, A[0]); \
            A[1] = ffma2(p1, W0, A[1]); A[1] = ffma2(p2, W1, A[1]); A[1] = ffma2(p3, W2, A[1]); \
            A[2] = ffma2(p2, W0, A[2]); A[2] = ffma2(p3, W1, A[2]); A[2] = ffma2(p4, W2, A[2]); \
            A[3] = ffma2(p3, W0, A[3]); A[3] = ffma2(p4, W1, A[3]); A[3] = ffma2(p5, W2, A[3]); \
            A[4] = ffma2(p4, W0, A[4]); A[4] = ffma2(p5, W1, A[4]); A[4] = ffma2(p6, W2, A[4]); \
            A[5] = ffma2(p5, W0, A[5]); A[5] = ffma2(p6, W1, A[5]); A[5] = ffma2(p7, W2, A[5]); \
            A[6] = ffma2(p6, W0, A[6]); A[6] = ffma2(p7, W1, A[6]); \
        } \
    } while (0)

    COMPUTE(0, a0, a1, a2);
    LOADW(a0, a1, a2, 3);                // chunk 3 hides behind compute 1+2
    COMPUTE(1, b0, b1, b2);
    COMPUTE(2, c0, c1, c2);
    COMPUTE(3, a0, a1, a2);

    // ---- epilogue: conflict-free reduce (overlays dead input smem) ----
    __syncthreads();                     // all warps done with input smem
    float2* red = reinterpret_cast<float2*>(sm + OFF_RED);
#pragma unroll
    for (int m = 0; m < 7; m++)
        red[warp * 224 + lane * 7 + m] = *reinterpret_cast<float2*>(&A[m]);
    __syncthreads();

    if (tid < 224) {                     // t = k*7 + m; reads lane-stride 8B
        float sx = 0.f, sy = 0.f;
#pragma unroll
        for (int is = 0; is < 16; is++) {
            float2 v = red[is * 224 + tid];
            sx += v.x; sy += v.y;
        }
        int k = tid / 7, m = tid - k * 7;
        int nOut = n + 1; if (nOut == 7) nOut = 0;     // height roll +1
        out[(k0 + k) * 49 + nOut * 7 + m]       = sx;  // group 0
        out[(512 + k0 + k) * 49 + nOut * 7 + m] = sy;  // group 1
    }
}

extern "C" void kernel_launch(void* const* d_in, const int* in_sizes, int n_in,
                              void* d_out, int out_size)
{
    const float* x = (const float*)d_in[0];
    const float* w = (const float*)d_in[1];
    float* out = (float*)d_out;

    conv_wp<<<dim3(16, 7), THREADS, SMEM_TOT>>>(x, w, out);
}